// round 10
// baseline (speedup 1.0000x reference)
#include <cuda_runtime.h>
#include <cstdint>

#define HH 256
#define WW 448
#define HW (HH * WW)
#define BB 2

typedef unsigned long long ull;

// ---------------- scratch (static device globals; alloc-free) ----------------
__device__ float g_ta [2 * BB * 64 * HW];  // conv1 out, both imgs / later h3
__device__ float g_tb [2 * BB * 64 * HW];  // conv2 out, both imgs
__device__ float g_ff [2 * BB * 32 * HW];  // conv3 out: f1 | f2
__device__ float g_f2w[BB * 32 * HW];
__device__ float g_cv [BB * 83 * HW];      // 81 cost + 2 flow channels
__device__ float g_h1 [BB * 128 * HW];
__device__ float g_h2 [BB * 128 * HW];
__device__ float g_wU [671744];            // winograd-transformed weights

// g_wU offsets (floats)
#define WU_C2 0
#define WU_C3 65536
#define WU_R1 98304
#define WU_R2 278528
#define WU_R3 540672

// ---------------- small PTX helpers ----------------
__device__ __forceinline__ unsigned smem_u32(const void* p) {
    unsigned a;
    asm("{ .reg .u64 t; cvta.to.shared.u64 t, %1; cvt.u32.u64 %0, t; }"
        : "=r"(a) : "l"(p));
    return a;
}
__device__ __forceinline__ void cp4(unsigned dst, const float* src, int srcsz) {
    asm volatile("cp.async.ca.shared.global [%0], [%1], 4, %2;"
                 :: "r"(dst), "l"(src), "r"(srcsz));
}
__device__ __forceinline__ void cp16(unsigned dst, const float* src) {
    asm volatile("cp.async.ca.shared.global [%0], [%1], 16;"
                 :: "r"(dst), "l"(src));
}
__device__ __forceinline__ void cp_commit() { asm volatile("cp.async.commit_group;"); }
__device__ __forceinline__ void cp_wait0()  { asm volatile("cp.async.wait_group 0;" ::: "memory"); }
__device__ __forceinline__ void cp_wait1()  { asm volatile("cp.async.wait_group 1;" ::: "memory"); }
__device__ __forceinline__ ull dupf(float x) {
    ull d;
    asm("mov.b64 %0, {%1,%1};" : "=l"(d) : "r"(__float_as_uint(x)));
    return d;
}

// ---------------- winograd weight transform: U = G w G^T ---------------------
// wt: [COUT][CIN][3][3]; U layout: [(g*NCH+cch)*2048 + d*128 + (ci%8)*16 + co]
__global__ void wino_wt_k(const float* __restrict__ wt, float* __restrict__ U,
                          int CIN, int CINP, int COUT)
{
    int idx = blockIdx.x * 256 + threadIdx.x;
    int total = (COUT / 16) * CINP * 16;
    if (idx >= total) return;
    int co = idx & 15;
    int ci = (idx >> 4) % CINP;
    int g  = idx / (16 * CINP);
    float u[4][4];
    if (ci < CIN) {
        const float* w = wt + (size_t)((g * 16 + co) * CIN + ci) * 9;
        float gw[4][3];
#pragma unroll
        for (int j = 0; j < 3; j++) {
            gw[0][j] = w[j];
            gw[1][j] = 0.5f * (w[j] + w[3 + j] + w[6 + j]);
            gw[2][j] = 0.5f * (w[j] - w[3 + j] + w[6 + j]);
            gw[3][j] = w[6 + j];
        }
#pragma unroll
        for (int i = 0; i < 4; i++) {
            u[i][0] = gw[i][0];
            u[i][1] = 0.5f * (gw[i][0] + gw[i][1] + gw[i][2]);
            u[i][2] = 0.5f * (gw[i][0] - gw[i][1] + gw[i][2]);
            u[i][3] = gw[i][2];
        }
    } else {
#pragma unroll
        for (int i = 0; i < 4; i++)
#pragma unroll
            for (int j = 0; j < 4; j++) u[i][j] = 0.f;
    }
    int nch = CINP >> 3;
    size_t base = (size_t)(g * nch + (ci >> 3)) * 2048 + (ci & 7) * 16 + co;
#pragma unroll
    for (int d = 0; d < 16; d++)
        U[base + (size_t)d * 128] = u[d >> 2][d & 3];
}

// ============ Winograd F(2x2,3x3) conv (+bias+relu), 1-bar pipelined =========
// block 256 thr; output tile 32x8 px = 64 wino tiles x 16 out channels.
// thread: d = tid>>4 (domain pt), sub = tid&15 -> 4 tiles x 16 co accumulators.
// smem (floats): raw db 2x3072 @0 | U db 2x2048 @6144 | V db 2x8192 @10240.
// M (epilogue) reuses sm[0..16384].
template <int CIN, int COUT, int NIMG>
__global__ void __launch_bounds__(256, 2)
conv3x3_wino(const float* __restrict__ in0,
             const float* __restrict__ in1,
             const float* __restrict__ Ubase,
             const float* __restrict__ bias,
             float* __restrict__ out)
{
    constexpr int CINP = (CIN + 7) & ~7;
    constexpr int NCH  = CINP / 8;
    constexpr int GROUPS = COUT / 16;
    extern __shared__ float sm[];
    constexpr int RAWO = 0;       // 2 * 8 * 384
    constexpr int UO   = 6144;    // 2 * 2048
    constexpr int VO   = 10240;   // 2 * 8192

    const int tid = threadIdx.x;
    const int d   = tid >> 4;     // 0..15
    const int sub = tid & 15;
    const int z   = blockIdx.z;
    const int img = (NIMG == 2) ? (z / (BB * GROUPS)) : 0;
    const int zr  = (NIMG == 2) ? (z % (BB * GROUPS)) : z;
    const int b   = zr / GROUPS;
    const int g   = zr % GROUPS;
    const int x0 = blockIdx.x * 32, y0 = blockIdx.y * 8;

    const float* inb = ((NIMG == 2 && img) ? in1 : in0) + (size_t)b * CIN * HW;
    const float* Ug  = Ubase + (size_t)g * NCH * 2048;
    const unsigned sbase = smem_u32(sm);

    // only 12 offset regs kept live; everything else recomputed per issue
    int goff[12];
#pragma unroll
    for (int j = 0; j < 12; j++) {
        int i = tid + 256 * j;
        int p = i / 360, s = i % 360;
        int r = s / 36, c = s % 36;
        int gy = y0 + r - 1, gx = x0 + c - 1;
        bool ok = (i < 2880) && (c < 34) &&
                  gy >= 0 && gy < HH && gx >= 0 && gx < WW;
        goff[j] = ok ? (p * HW + gy * WW + gx) : -1;
    }

    auto issue_raw = [&](int c) {
        const unsigned rb = sbase + (unsigned)(RAWO + (c & 1) * 3072) * 4u;
        const float* src0 = inb + (size_t)c * 8 * HW;
#pragma unroll
        for (int j = 0; j < 12; j++) {
            int i = tid + 256 * j;
            if (j < 11 || i < 2880) {
                int p = i / 360;                 // recomputed (const-div)
                int off = goff[j];
                int sz = (off >= 0) ? 4 : 0;
                if (CIN != CINP) { if (c * 8 + p >= CIN) sz = 0; }
                cp4(rb + (unsigned)(i + 24 * p) * 4u,
                    src0 + (sz ? off : 0), sz);
            }
        }
    };
    auto issue_U = [&](int c) {
        const unsigned ub = sbase + (unsigned)(UO + (c & 1) * 2048) * 4u;
        const float* us = Ug + (size_t)c * 2048 + tid * 8;
        cp16(ub + (unsigned)(tid * 8) * 4u, us);
        cp16(ub + (unsigned)(tid * 8 + 4) * 4u, us + 4);
    };

    auto transform = [&](int c) {
        const float* rawb = sm + RAWO + (c & 1) * 3072;
        float* vbase = sm + VO + (c & 1) * 8192;
#pragma unroll
        for (int k = 0; k < 2; k++) {
            int item = tid + 256 * k;
            int tile = item & 63;
            int ci   = item >> 6;         // 0..7
            const float* rb = rawb + ci * 384 + (tile >> 4) * 72 + (tile & 15) * 2;
            float din[4][4];
#pragma unroll
            for (int r = 0; r < 4; r++)
#pragma unroll
                for (int cc = 0; cc < 4; cc++)
                    din[r][cc] = rb[r * 36 + cc];
            float TD[4][4];
#pragma unroll
            for (int cc = 0; cc < 4; cc++) {
                TD[0][cc] = din[0][cc] - din[2][cc];
                TD[1][cc] = din[1][cc] + din[2][cc];
                TD[2][cc] = din[2][cc] - din[1][cc];
                TD[3][cc] = din[1][cc] - din[3][cc];
            }
            float* vb = vbase + ci * 64 + tile;
#pragma unroll
            for (int r = 0; r < 4; r++) {
                vb[(r * 4 + 0) * 512] = TD[r][0] - TD[r][2];
                vb[(r * 4 + 1) * 512] = TD[r][1] + TD[r][2];
                vb[(r * 4 + 2) * 512] = TD[r][2] - TD[r][1];
                vb[(r * 4 + 3) * 512] = TD[r][1] - TD[r][3];
            }
        }
    };

    ull acc[4][8];
#pragma unroll
    for (int i = 0; i < 4; i++)
#pragma unroll
        for (int j = 0; j < 8; j++) acc[i][j] = 0ULL;

    // ---- prologue: raw0+U0 (group), raw1 (group), transform(0) ----
    issue_raw(0); issue_U(0); cp_commit();
    issue_raw(1); cp_commit();
    cp_wait1();                 // raw0 + U0 complete
    __syncthreads();
    transform(0);

    for (int c = 0; c < NCH; c++) {
        cp_wait0();             // chunk c+1 raw (+U) complete
        __syncthreads();        // visibility: raw(c+1), V(c), and V/raw reuse
        bool committed = false;
        if (c + 2 < NCH) { issue_raw(c + 2); committed = true; }
        if (c + 1 < NCH) { issue_U(c + 1); committed = true; }
        if (committed) cp_commit();
        if (c + 1 < NCH) transform(c + 1);

        // ---- GEMM in winograd domain ----
        const float* Ub = sm + UO + (c & 1) * 2048 + d * 128;
        const float* Vb = sm + VO + (c & 1) * 8192 + d * 512 + 4 * sub;
#pragma unroll
        for (int ci = 0; ci < 8; ci++) {
            float4 v4 = *reinterpret_cast<const float4*>(Vb + ci * 64);
            ull dv[4];
            dv[0] = dupf(v4.x); dv[1] = dupf(v4.y);
            dv[2] = dupf(v4.z); dv[3] = dupf(v4.w);
            const ulonglong2* uu =
                reinterpret_cast<const ulonglong2*>(Ub + ci * 16);
#pragma unroll
            for (int q = 0; q < 4; q++) {
                ulonglong2 wv = uu[q];
#pragma unroll
                for (int i = 0; i < 4; i++) {
                    asm("fma.rn.f32x2 %0, %1, %2, %0;"
                        : "+l"(acc[i][q * 2    ]) : "l"(dv[i]), "l"(wv.x));
                    asm("fma.rn.f32x2 %0, %1, %2, %0;"
                        : "+l"(acc[i][q * 2 + 1]) : "l"(dv[i]), "l"(wv.y));
                }
            }
        }
    }
    __syncthreads();   // all GEMM done; raw/U/V dead -> reuse as M

    // ---- hand off M[d][tile][co16] through smem ----
    float* M = sm;
#pragma unroll
    for (int i = 0; i < 4; i++) {
        int tile = 4 * sub + i;
        ulonglong2* mrow =
            reinterpret_cast<ulonglong2*>(M + (d * 64 + tile) * 16);
#pragma unroll
        for (int q = 0; q < 4; q++) {
            ulonglong2 v; v.x = acc[i][q * 2]; v.y = acc[i][q * 2 + 1];
            mrow[q] = v;
        }
    }
    __syncthreads();

    // ---- output transform: A^T M A + bias + relu ----
    const int co = tid & 15;
    const int tb = tid >> 4;
    const float bv = bias[g * 16 + co];
    float* ob = out + (size_t)img * ((size_t)BB * COUT * HW)
                    + ((size_t)b * COUT + g * 16 + co) * HW;
#pragma unroll
    for (int k = 0; k < 4; k++) {
        int tile = tb + 16 * k;
        float m[16];
#pragma unroll
        for (int dd = 0; dd < 16; dd++)
            m[dd] = M[(dd * 64 + tile) * 16 + co];
        float T0[4], T1[4];
#pragma unroll
        for (int cc = 0; cc < 4; cc++) {
            T0[cc] = m[cc] + m[4 + cc] + m[8 + cc];
            T1[cc] = m[4 + cc] - m[8 + cc] - m[12 + cc];
        }
        float y00 = T0[0] + T0[1] + T0[2] + bv;
        float y01 = T0[1] - T0[2] - T0[3] + bv;
        float y10 = T1[0] + T1[1] + T1[2] + bv;
        float y11 = T1[1] - T1[2] - T1[3] + bv;
        y00 = fmaxf(y00, 0.f); y01 = fmaxf(y01, 0.f);
        y10 = fmaxf(y10, 0.f); y11 = fmaxf(y11, 0.f);
        int y = y0 + (tile >> 4) * 2, x = x0 + (tile & 15) * 2;
        *reinterpret_cast<float2*>(ob + (size_t)y * WW + x) = make_float2(y00, y01);
        *reinterpret_cast<float2*>(ob + (size_t)(y + 1) * WW + x) = make_float2(y10, y11);
    }
}

// ============ packed-f32x2 direct 3x3 conv (layer c1 only, CIN=3) ============
template <int CIN, int COUT, bool RELU, int NIMG>
__global__ void __launch_bounds__(256)
conv3x3_p2(const float* __restrict__ in0,
           const float* __restrict__ in1,
           const float* __restrict__ wt,
           const float* __restrict__ bias,
           float* __restrict__ out)
{
    constexpr int CT   = 16;
    constexpr int CINP = (CIN + 1) & ~1;
    constexpr int NC   = CINP / 2;
    constexpr int PL   = 1280;
    constexpr int GROUPS = COUT / CT;
    extern __shared__ float sm[];
    float* w_s  = sm;
    float* in_s = sm + CINP * 144;

    const int tid = threadIdx.x;
    const int tx4 = tid & 15;
    const int ty  = tid >> 4;
    const int z   = blockIdx.z;
    const int img = (NIMG == 2) ? (z / (BB * GROUPS)) : 0;
    const int zr  = (NIMG == 2) ? (z % (BB * GROUPS)) : z;
    const int b   = zr / GROUPS;
    const int co0 = (zr % GROUPS) * CT;
    const int x0 = blockIdx.x * 64, y0 = blockIdx.y * 16;

    for (int i = tid; i < CINP * 144; i += 256) {
        int col  = i % CT;
        int rest = i / CT;
        int k    = rest % 9;
        int ci   = rest / 9;
        w_s[i] = (ci < CIN) ? wt[((co0 + col) * CIN + ci) * 9 + k] : 0.f;
    }

    const float* inb = ((NIMG == 2 && img) ? in1 : in0) + (size_t)b * CIN * HW;
    int goff[5], vsz[5];
#pragma unroll
    for (int j = 0; j < 5; j++) {
        int idx = tid + 256 * j;
        int r = idx / 68, cc = idx % 68;
        int gy = y0 + r - 1, gx = x0 + cc - 1;
        bool ok = (idx < 18 * 68) && (cc < 66) &&
                  gy >= 0 && gy < HH && gx >= 0 && gx < WW;
        goff[j] = ok ? (gy * WW + gx) : 0;
        vsz[j]  = ok ? 4 : 0;
    }
    const unsigned sbase = smem_u32(in_s);

    auto issue = [&](int c) {
        const unsigned cb = sbase + (unsigned)((c & 1) * 2 * PL) * 4u;
#pragma unroll
        for (int p = 0; p < 2; p++) {
            int ci = c * 2 + p;
            const float* src = inb + (size_t)ci * HW;
            int pok = (ci < CIN) ? 1 : 0;
#pragma unroll
            for (int j = 0; j < 5; j++)
                cp4(cb + (unsigned)(p * PL + tid + 256 * j) * 4u,
                    src + goff[j], pok ? vsz[j] : 0);
        }
        cp_commit();
    };

    ull acc[4][8];
#pragma unroll
    for (int px = 0; px < 4; px++)
#pragma unroll
        for (int j = 0; j < 8; j++) acc[px][j] = 0ULL;

    issue(0);

    for (int c = 0; c < NC; c++) {
        cp_wait0();
        __syncthreads();
        if (c + 1 < NC) issue(c + 1);

        const float* buf = in_s + (c & 1) * 2 * PL;
#pragma unroll
        for (int p = 0; p < 2; p++) {
            const float* wpl = w_s + (size_t)(c * 2 + p) * 144;
#pragma unroll
            for (int ky = 0; ky < 3; ky++) {
                const float* rp = buf + p * PL + (ty + ky) * 68 + tx4 * 4;
                float4 lo = *reinterpret_cast<const float4*>(rp);
                float2 hi = *reinterpret_cast<const float2*>(rp + 4);
                ull dv[6];
                dv[0] = dupf(lo.x); dv[1] = dupf(lo.y); dv[2] = dupf(lo.z);
                dv[3] = dupf(lo.w); dv[4] = dupf(hi.x); dv[5] = dupf(hi.y);
#pragma unroll
                for (int kx = 0; kx < 3; kx++) {
                    const ulonglong2* wk =
                        reinterpret_cast<const ulonglong2*>(wpl + (ky * 3 + kx) * CT);
#pragma unroll
                    for (int q = 0; q < 4; q++) {
                        ulonglong2 wv = wk[q];
#pragma unroll
                        for (int px = 0; px < 4; px++) {
                            asm("fma.rn.f32x2 %0, %1, %2, %0;"
                                : "+l"(acc[px][q * 2    ]) : "l"(dv[kx + px]), "l"(wv.x));
                            asm("fma.rn.f32x2 %0, %1, %2, %0;"
                                : "+l"(acc[px][q * 2 + 1]) : "l"(dv[kx + px]), "l"(wv.y));
                        }
                    }
                }
            }
        }
        __syncthreads();
    }

    float* ob = out + (size_t)img * ((size_t)BB * COUT * HW);
    const int y = y0 + ty, x = x0 + tx4 * 4;
#pragma unroll
    for (int j = 0; j < 8; j++) {
        float c0[4], c1[4];
#pragma unroll
        for (int px = 0; px < 4; px++) {
            unsigned plo, phi;
            asm("mov.b64 {%0,%1}, %2;" : "=r"(plo), "=r"(phi) : "l"(acc[px][j]));
            c0[px] = __uint_as_float(plo);
            c1[px] = __uint_as_float(phi);
        }
        float b0 = bias[co0 + 2 * j], b1 = bias[co0 + 2 * j + 1];
#pragma unroll
        for (int px = 0; px < 4; px++) {
            c0[px] += b0; c1[px] += b1;
            if constexpr (RELU) { c0[px] = fmaxf(c0[px], 0.f); c1[px] = fmaxf(c1[px], 0.f); }
        }
        float* o0 = ob + ((size_t)b * COUT + co0 + 2 * j) * HW + y * WW + x;
        float* o1 = ob + ((size_t)b * COUT + co0 + 2 * j + 1) * HW + y * WW + x;
        *reinterpret_cast<float4*>(o0) = make_float4(c0[0], c0[1], c0[2], c0[3]);
        *reinterpret_cast<float4*>(o1) = make_float4(c1[0], c1[1], c1[2], c1[3]);
    }
}

// ---------------- scalar 3x3 conv (tiny 64->2 final layer + residual) --------
template <int CIN, int COUT, int CT, bool RELU, bool ADDIN>
__global__ void conv3x3_k(const float* __restrict__ in,
                          const float* __restrict__ wt,
                          const float* __restrict__ bias,
                          const float* __restrict__ res,
                          float* __restrict__ out)
{
    extern __shared__ float sm[];
    float* w_s  = sm;
    float* in_s = sm + CIN * 9 * CT;

    const int tid = threadIdx.x;
    const int tx = tid & 31, ty = tid >> 5;
    const int groups = COUT / CT;
    const int b   = blockIdx.z / groups;
    const int co0 = (blockIdx.z % groups) * CT;
    const int x0 = blockIdx.x * 32, y0 = blockIdx.y * 8;

    const int WN = CIN * 9 * CT;
    for (int i = tid; i < WN; i += 256) {
        int col  = i % CT;
        int rest = i / CT;
        int k    = rest % 9;
        int ci   = rest / 9;
        w_s[i] = wt[((co0 + col) * CIN + ci) * 9 + k];
    }

    float acc[CT];
#pragma unroll
    for (int c = 0; c < CT; c++) acc[c] = 0.f;

    const float* inb = in + (size_t)b * CIN * HW;

    for (int ci0 = 0; ci0 < CIN; ci0 += 8) {
        const int chunk = (CIN - ci0 < 8) ? (CIN - ci0) : 8;
        __syncthreads();
        for (int i = tid; i < chunk * 340; i += 256) {
            int p  = i / 340;
            int r  = (i % 340) / 34;
            int cc = (i % 340) % 34;
            int gy = y0 + r - 1, gx = x0 + cc - 1;
            float v = 0.f;
            if (gy >= 0 && gy < HH && gx >= 0 && gx < WW)
                v = inb[(size_t)(ci0 + p) * HW + gy * WW + gx];
            in_s[i] = v;
        }
        __syncthreads();

        for (int p = 0; p < chunk; ++p) {
            float v[9];
#pragma unroll
            for (int ky = 0; ky < 3; ky++)
#pragma unroll
                for (int kx = 0; kx < 3; kx++)
                    v[ky * 3 + kx] = in_s[p * 340 + (ty + ky) * 34 + tx + kx];

            const float* wp = w_s + (size_t)(ci0 + p) * 9 * CT;
#pragma unroll
            for (int k = 0; k < 9; k++) {
                float vv = v[k];
#pragma unroll
                for (int c = 0; c < CT; c++) acc[c] += vv * wp[k * CT + c];
            }
        }
    }

    const int y = y0 + ty, x = x0 + tx;
#pragma unroll
    for (int c = 0; c < CT; c++) {
        float r = acc[c] + bias[co0 + c];
        if constexpr (RELU) r = fmaxf(r, 0.f);
        if constexpr (ADDIN) r += res[((size_t)b * COUT + co0 + c) * HW + y * WW + x];
        out[((size_t)b * COUT + co0 + c) * HW + y * WW + x] = r;
    }
}

// ---------------- bilinear warp of f2 by initial flow (border clamp) ---------
__global__ void warp_k(const float* __restrict__ f2,
                       const float* __restrict__ flow,
                       float* __restrict__ f2w)
{
    int x = blockIdx.x * 32 + (threadIdx.x & 31);
    int y = blockIdx.y * 8 + (threadIdx.x >> 5);
    int b = blockIdx.z;
    int pix = y * WW + x;
    float fx = (float)x + flow[((size_t)b * 2 + 0) * HW + pix];
    float fy = (float)y + flow[((size_t)b * 2 + 1) * HW + pix];
    fx = fminf(fmaxf(fx, 0.f), (float)(WW - 1));
    fy = fminf(fmaxf(fy, 0.f), (float)(HH - 1));
    float x0f = floorf(fx), y0f = floorf(fy);
    int x0 = (int)x0f, y0i = (int)y0f;
    int x1 = min(x0 + 1, WW - 1), y1 = min(y0i + 1, HH - 1);
    float wx = fx - x0f, wy = fy - y0f;
    float w00 = (1.f - wx) * (1.f - wy), w01 = wx * (1.f - wy);
    float w10 = (1.f - wx) * wy,        w11 = wx * wy;
    const float* fb = f2 + (size_t)b * 32 * HW;
    float* ob = f2w + (size_t)b * 32 * HW + pix;
#pragma unroll 8
    for (int c = 0; c < 32; c++) {
        const float* p = fb + (size_t)c * HW;
        float v = w00 * p[y0i * WW + x0] + w01 * p[y0i * WW + x1]
                + w10 * p[y1  * WW + x0] + w11 * p[y1  * WW + x1];
        ob[(size_t)c * HW] = v;
    }
}

// ---------------- cost volume: 2 px/thread, packed FFMA2; folds flow concat ---
__global__ void __launch_bounds__(128)
costvol_k(const float* __restrict__ f1,
          const float* __restrict__ f2w,
          const float* __restrict__ flow,
          float* __restrict__ cv)
{
    extern __shared__ float s[]; // 32*16*40
    const int tid = threadIdx.x;
    const int txi = tid & 15;
    const int ty  = tid >> 4;
    const int b = blockIdx.z;
    const int x0 = blockIdx.x * 32, y0 = blockIdx.y * 8;
    const float* f2b = f2w + (size_t)b * 32 * HW;
    for (int i = tid; i < 32 * 16 * 40; i += 128) {
        int c  = i / 640;
        int r  = (i % 640) / 40;
        int cc = i % 640 % 40;
        int gy = min(max(y0 + r - 4, 0), HH - 1);
        int gx = min(max(x0 + cc - 4, 0), WW - 1);
        s[i] = f2b[(size_t)c * HW + gy * WW + gx];
    }
    __syncthreads();

    const int y = y0 + ty, x = x0 + txi * 2;
    const int pix = y * WW + x;

    ull f1p[32];
    const float* f1b = f1 + (size_t)b * 32 * HW + pix;
#pragma unroll
    for (int c = 0; c < 32; c++)
        f1p[c] = *reinterpret_cast<const ull*>(f1b + (size_t)c * HW);

    float* cvb = cv + (size_t)b * 83 * HW + pix;

    for (int dy = 0; dy < 9; dy++) {
        ull acc[9];
#pragma unroll
        for (int dx = 0; dx < 9; dx++) acc[dx] = 0ULL;

        const float* rowp = s + (ty + dy) * 40 + txi * 2;
        for (int c = 0; c < 32; c++) {
            const float* sp = rowp + c * 640;
            float2 L0 = *reinterpret_cast<const float2*>(sp);
            float2 L1 = *reinterpret_cast<const float2*>(sp + 2);
            float2 L2 = *reinterpret_cast<const float2*>(sp + 4);
            float2 L3 = *reinterpret_cast<const float2*>(sp + 6);
            float2 L4 = *reinterpret_cast<const float2*>(sp + 8);
            ull P0 = *reinterpret_cast<const ull*>(&L0);
            ull P2 = *reinterpret_cast<const ull*>(&L1);
            ull P4 = *reinterpret_cast<const ull*>(&L2);
            ull P6 = *reinterpret_cast<const ull*>(&L3);
            ull P8 = *reinterpret_cast<const ull*>(&L4);
            ull P1, P3, P5, P7;
            asm("mov.b64 %0, {%1,%2};" : "=l"(P1)
                : "r"(__float_as_uint(L0.y)), "r"(__float_as_uint(L1.x)));
            asm("mov.b64 %0, {%1,%2};" : "=l"(P3)
                : "r"(__float_as_uint(L1.y)), "r"(__float_as_uint(L2.x)));
            asm("mov.b64 %0, {%1,%2};" : "=l"(P5)
                : "r"(__float_as_uint(L2.y)), "r"(__float_as_uint(L3.x)));
            asm("mov.b64 %0, {%1,%2};" : "=l"(P7)
                : "r"(__float_as_uint(L3.y)), "r"(__float_as_uint(L4.x)));
            ull fp = f1p[c];
            asm("fma.rn.f32x2 %0, %1, %2, %0;" : "+l"(acc[0]) : "l"(fp), "l"(P0));
            asm("fma.rn.f32x2 %0, %1, %2, %0;" : "+l"(acc[1]) : "l"(fp), "l"(P1));
            asm("fma.rn.f32x2 %0, %1, %2, %0;" : "+l"(acc[2]) : "l"(fp), "l"(P2));
            asm("fma.rn.f32x2 %0, %1, %2, %0;" : "+l"(acc[3]) : "l"(fp), "l"(P3));
            asm("fma.rn.f32x2 %0, %1, %2, %0;" : "+l"(acc[4]) : "l"(fp), "l"(P4));
            asm("fma.rn.f32x2 %0, %1, %2, %0;" : "+l"(acc[5]) : "l"(fp), "l"(P5));
            asm("fma.rn.f32x2 %0, %1, %2, %0;" : "+l"(acc[6]) : "l"(fp), "l"(P6));
            asm("fma.rn.f32x2 %0, %1, %2, %0;" : "+l"(acc[7]) : "l"(fp), "l"(P7));
            asm("fma.rn.f32x2 %0, %1, %2, %0;" : "+l"(acc[8]) : "l"(fp), "l"(P8));
        }
#pragma unroll
        for (int dx = 0; dx < 9; dx++) {
            unsigned plo, phi;
            asm("mov.b64 {%0,%1}, %2;" : "=r"(plo), "=r"(phi) : "l"(acc[dx]));
            *reinterpret_cast<float2*>(cvb + (size_t)(dy * 9 + dx) * HW) =
                make_float2(__uint_as_float(plo), __uint_as_float(phi));
        }
    }

    const float* flb = flow + (size_t)b * 2 * HW + pix;
    *reinterpret_cast<float2*>(cvb + (size_t)81 * HW) =
        *reinterpret_cast<const float2*>(flb);
    *reinterpret_cast<float2*>(cvb + (size_t)82 * HW) =
        *reinterpret_cast<const float2*>(flb + HW);
}

// ---------------- host launch -------------------------------------------------
static inline int smem_p2(int cin) {
    int cinp = (cin + 1) & ~1;
    return (cinp * 144 + 2 * 2 * 1280) * 4;
}
static inline int smem_sc(int cin, int ct) { return (cin * 9 * ct + 8 * 340) * 4; }
#define SMEM_WINO (26624 * 4)

extern "C" void kernel_launch(void* const* d_in, const int* in_sizes, int n_in,
                              void* d_out, int out_size)
{
    const float* feat1 = (const float*)d_in[0];
    const float* feat2 = (const float*)d_in[1];
    const float* iflow = (const float*)d_in[2];
    const float* fW1 = (const float*)d_in[3];  const float* fb1 = (const float*)d_in[4];
    const float* fW2 = (const float*)d_in[5];  const float* fb2 = (const float*)d_in[6];
    const float* fW3 = (const float*)d_in[7];  const float* fb3 = (const float*)d_in[8];
    const float* rW1 = (const float*)d_in[9];  const float* rb1 = (const float*)d_in[10];
    const float* rW2 = (const float*)d_in[11]; const float* rb2 = (const float*)d_in[12];
    const float* rW3 = (const float*)d_in[13]; const float* rb3 = (const float*)d_in[14];
    const float* rW4 = (const float*)d_in[15]; const float* rb4 = (const float*)d_in[16];
    float* out = (float*)d_out;

    float *ta, *tb, *ff, *f2w, *cv, *h1, *h2, *wU;
    cudaGetSymbolAddress((void**)&ta,  g_ta);
    cudaGetSymbolAddress((void**)&tb,  g_tb);
    cudaGetSymbolAddress((void**)&ff,  g_ff);
    cudaGetSymbolAddress((void**)&f2w, g_f2w);
    cudaGetSymbolAddress((void**)&cv,  g_cv);
    cudaGetSymbolAddress((void**)&h1,  g_h1);
    cudaGetSymbolAddress((void**)&h2,  g_h2);
    cudaGetSymbolAddress((void**)&wU,  g_wU);

    cudaFuncSetAttribute((const void*)conv3x3_p2<3, 64, true, 2>,
                         cudaFuncAttributeMaxDynamicSharedMemorySize, smem_p2(3));
    cudaFuncSetAttribute((const void*)conv3x3_wino<64, 64, 2>,
                         cudaFuncAttributeMaxDynamicSharedMemorySize, SMEM_WINO);
    cudaFuncSetAttribute((const void*)conv3x3_wino<64, 32, 2>,
                         cudaFuncAttributeMaxDynamicSharedMemorySize, SMEM_WINO);
    cudaFuncSetAttribute((const void*)conv3x3_wino<83, 128, 1>,
                         cudaFuncAttributeMaxDynamicSharedMemorySize, SMEM_WINO);
    cudaFuncSetAttribute((const void*)conv3x3_wino<128, 128, 1>,
                         cudaFuncAttributeMaxDynamicSharedMemorySize, SMEM_WINO);
    cudaFuncSetAttribute((const void*)conv3x3_wino<128, 64, 1>,
                         cudaFuncAttributeMaxDynamicSharedMemorySize, SMEM_WINO);
    cudaFuncSetAttribute((const void*)costvol_k,
                         cudaFuncAttributeMaxDynamicSharedMemorySize, 32 * 16 * 40 * 4);

    dim3 blk(256);
    const int PXg = WW / 64, PYg = HH / 16;  // 7, 16 (direct conv grid)
    const int SX = WW / 32, SY = HH / 8;     // 14, 32 (wino / scalar grid)

    // ---- winograd weight transforms (tiny) ----
    wino_wt_k<<<(4 * 64 * 16 + 255) / 256, 256>>>(fW2, wU + WU_C2, 64, 64, 64);
    wino_wt_k<<<(2 * 64 * 16 + 255) / 256, 256>>>(fW3, wU + WU_C3, 64, 64, 32);
    wino_wt_k<<<(8 * 88 * 16 + 255) / 256, 256>>>(rW1, wU + WU_R1, 83, 88, 128);
    wino_wt_k<<<(8 * 128 * 16 + 255) / 256, 256>>>(rW2, wU + WU_R2, 128, 128, 128);
    wino_wt_k<<<(4 * 128 * 16 + 255) / 256, 256>>>(rW3, wU + WU_R3, 128, 128, 64);

    // ---- feature extraction ----
    conv3x3_p2<3, 64, true, 2><<<dim3(PXg, PYg, 2 * BB * 4), blk, smem_p2(3)>>>(
        feat1, feat2, fW1, fb1, ta);
    conv3x3_wino<64, 64, 2><<<dim3(SX, SY, 2 * BB * 4), blk, SMEM_WINO>>>(
        ta, ta + (size_t)BB * 64 * HW, wU + WU_C2, fb2, tb);
    conv3x3_wino<64, 32, 2><<<dim3(SX, SY, 2 * BB * 2), blk, SMEM_WINO>>>(
        tb, tb + (size_t)BB * 64 * HW, wU + WU_C3, fb3, ff);

    const float* f1 = ff;
    const float* f2 = ff + (size_t)BB * 32 * HW;

    // ---- warp + cost volume ----
    warp_k<<<dim3(SX, SY, BB), blk>>>(f2, iflow, f2w);
    costvol_k<<<dim3(SX, SY, BB), dim3(128), 32 * 16 * 40 * 4>>>(f1, f2w, iflow, cv);

    // ---- refinement ----
    conv3x3_wino<83, 128, 1><<<dim3(SX, SY, BB * 8), blk, SMEM_WINO>>>(
        cv, cv, wU + WU_R1, rb1, h1);
    conv3x3_wino<128, 128, 1><<<dim3(SX, SY, BB * 8), blk, SMEM_WINO>>>(
        h1, h1, wU + WU_R2, rb2, h2);
    conv3x3_wino<128, 64, 1><<<dim3(SX, SY, BB * 4), blk, SMEM_WINO>>>(
        h2, h2, wU + WU_R3, rb3, ta);
    conv3x3_k<64, 2, 2, false, true><<<dim3(SX, SY, BB), blk, smem_sc(64, 2)>>>(
        ta, rW4, rb4, iflow, out);
}

// round 14
// speedup vs baseline: 1.1244x; 1.1244x over previous
#include <cuda_runtime.h>
#include <cstdint>

#define HH 256
#define WW 448
#define HW (HH * WW)
#define BB 2

typedef unsigned long long ull;

// ---------------- scratch (static device globals; alloc-free) ----------------
__device__ float g_ta [2 * BB * 64 * HW];  // conv1 out, both imgs / later h3
__device__ float g_tb [2 * BB * 64 * HW];  // conv2 out, both imgs
__device__ float g_ff [2 * BB * 32 * HW];  // conv3 out: f1 | f2
__device__ float g_f2w[BB * 32 * HW];
__device__ float g_cv [BB * 83 * HW];      // 81 cost + 2 flow channels
__device__ float g_h1 [BB * 128 * HW];
__device__ float g_h2 [BB * 128 * HW];
__device__ __align__(16) float g_wr[375552];   // reordered conv weights

// g_wr offsets (floats)
#define WR_C1 0
#define WR_C2 2304
#define WR_C3 39168
#define WR_R1 57600
#define WR_R2 154368
#define WR_R3 301824

// ---------------- small PTX helpers ----------------
__device__ __forceinline__ unsigned smem_u32(const void* p) {
    unsigned a;
    asm("{ .reg .u64 t; cvta.to.shared.u64 t, %1; cvt.u32.u64 %0, t; }"
        : "=r"(a) : "l"(p));
    return a;
}
__device__ __forceinline__ void cp4(unsigned dst, const float* src, int srcsz) {
    asm volatile("cp.async.ca.shared.global [%0], [%1], 4, %2;"
                 :: "r"(dst), "l"(src), "r"(srcsz));
}
__device__ __forceinline__ void cp16(unsigned dst, const float4* src) {
    asm volatile("cp.async.ca.shared.global [%0], [%1], 16;"
                 :: "r"(dst), "l"(src));
}
__device__ __forceinline__ void cp_commit() { asm volatile("cp.async.commit_group;"); }
__device__ __forceinline__ void cp_wait0()  { asm volatile("cp.async.wait_group 0;" ::: "memory"); }
__device__ __forceinline__ void cp_wait1()  { asm volatile("cp.async.wait_group 1;" ::: "memory"); }
__device__ __forceinline__ ull dupf(float x) {
    ull d;
    asm("mov.b64 %0, {%1,%1};" : "=l"(d) : "r"(__float_as_uint(x)));
    return d;
}

// ---------------- weight reorder: wt[co][ci][9] -> wr[g][ci][k][col16] --------
__global__ void wreorder_k(const float* __restrict__ wt, float* __restrict__ out,
                           int CIN, int CINP, int n)
{
    int i = blockIdx.x * 256 + threadIdx.x;
    if (i >= n) return;
    int col = i % 16;
    int k   = (i / 16) % 9;
    int ci  = (i / 144) % CINP;
    int g   = i / (144 * CINP);
    out[i] = (ci < CIN) ? wt[((g * 16 + col) * CIN + ci) * 9 + k] : 0.f;
}

// ============ packed-f32x2 3x3 SAME conv, 4-buffer cp.async ring =============
// block 256 thr; tile 64x16 px; thread = 4 consecutive px x 16 out channels.
// smem: reordered weights [ci][k][col16] (cp.async-staged, overlapped with
// chunk 0) + 4 input buffers of 2 planes x 1280 floats. One bar per chunk.
template <int CIN, int COUT, bool RELU, int NIMG>
__global__ void __launch_bounds__(256)
conv3x3_p2(const float* __restrict__ in0,
           const float* __restrict__ in1,
           const float* __restrict__ wr,
           const float* __restrict__ bias,
           float* __restrict__ out)
{
    constexpr int CT   = 16;
    constexpr int CINP = (CIN + 1) & ~1;
    constexpr int NC   = CINP / 2;            // chunks of 2 planes
    constexpr int PL   = 1280;                // plane stride (floats)
    constexpr int GROUPS = COUT / CT;
    extern __shared__ float sm[];
    float* w_s  = sm;                         // CINP*144
    float* in_s = sm + CINP * 144;            // 4 * 2 * PL

    const int tid = threadIdx.x;
    const int tx4 = tid & 15;                 // x-group (4 px each)
    const int ty  = tid >> 4;                 // row 0..15
    const int z   = blockIdx.z;
    const int img = (NIMG == 2) ? (z / (BB * GROUPS)) : 0;
    const int zr  = (NIMG == 2) ? (z % (BB * GROUPS)) : z;
    const int b   = zr / GROUPS;
    const int g   = zr % GROUPS;
    const int co0 = g * CT;
    const int x0 = blockIdx.x * 64, y0 = blockIdx.y * 16;

    // weight staging: pure cp.async.16, joins the first commit group below
    {
        const float4* wsrc =
            reinterpret_cast<const float4*>(wr + (size_t)g * CINP * 144);
        const unsigned wbase = smem_u32(w_s);
        for (int i = tid; i < CINP * 36; i += 256)
            cp16(wbase + (unsigned)i * 16u, wsrc + i);
    }

    // per-thread input load slots (computed once): 5 x (gmem offset, size)
    const float* inb = ((NIMG == 2 && img) ? in1 : in0) + (size_t)b * CIN * HW;
    int goff[5], vsz[5];
#pragma unroll
    for (int j = 0; j < 5; j++) {
        int idx = tid + 256 * j;
        int r = idx / 68, cc = idx % 68;
        int gy = y0 + r - 1, gx = x0 + cc - 1;
        bool ok = (idx < 18 * 68) && (cc < 66) &&
                  gy >= 0 && gy < HH && gx >= 0 && gx < WW;
        goff[j] = ok ? (gy * WW + gx) : 0;
        vsz[j]  = ok ? 4 : 0;
    }
    const unsigned sbase = smem_u32(in_s);

    auto issue = [&](int c) {
        const unsigned cb = sbase + (unsigned)((c & 3) * 2 * PL) * 4u;
#pragma unroll
        for (int p = 0; p < 2; p++) {
            int ci = c * 2 + p;
            const float* src = inb + (size_t)ci * HW;
            int pok = (ci < CIN) ? 1 : 0;
#pragma unroll
            for (int j = 0; j < 5; j++)
                cp4(cb + (unsigned)(p * PL + tid + 256 * j) * 4u,
                    src + goff[j], pok ? vsz[j] : 0);
        }
        cp_commit();
    };

    ull acc[4][8];                            // [pixel][channel pair]
#pragma unroll
    for (int px = 0; px < 4; px++)
#pragma unroll
        for (int j = 0; j < 8; j++) acc[px][j] = 0ULL;

    issue(0);                                 // group0 = weights + chunk0
    if (NC > 1) issue(1);

    for (int c = 0; c < NC; c++) {
        if (c + 1 < NC) cp_wait1(); else cp_wait0();
        __syncthreads();                      // single bar per chunk
        if (c + 2 < NC) issue(c + 2);

        const float* buf = in_s + (c & 3) * 2 * PL;
#pragma unroll
        for (int p = 0; p < 2; p++) {
            const float* wpl = w_s + (size_t)(c * 2 + p) * 144;
#pragma unroll
            for (int ky = 0; ky < 3; ky++) {
                const float* rp = buf + p * PL + (ty + ky) * 68 + tx4 * 4;
                float4 lo = *reinterpret_cast<const float4*>(rp);      // v0..v3
                float2 hi = *reinterpret_cast<const float2*>(rp + 4);  // v4,v5
                ull dv[6];
                dv[0] = dupf(lo.x); dv[1] = dupf(lo.y); dv[2] = dupf(lo.z);
                dv[3] = dupf(lo.w); dv[4] = dupf(hi.x); dv[5] = dupf(hi.y);
#pragma unroll
                for (int kx = 0; kx < 3; kx++) {
                    const ulonglong2* wk =
                        reinterpret_cast<const ulonglong2*>(wpl + (ky * 3 + kx) * CT);
#pragma unroll
                    for (int q = 0; q < 4; q++) {
                        ulonglong2 wv = wk[q];   // 4 out channels = 2 pairs
#pragma unroll
                        for (int px = 0; px < 4; px++) {
                            asm("fma.rn.f32x2 %0, %1, %2, %0;"
                                : "+l"(acc[px][q * 2    ]) : "l"(dv[kx + px]), "l"(wv.x));
                            asm("fma.rn.f32x2 %0, %1, %2, %0;"
                                : "+l"(acc[px][q * 2 + 1]) : "l"(dv[kx + px]), "l"(wv.y));
                        }
                    }
                }
            }
        }
    }

    // epilogue: unpack, add bias, relu, store 4-px float4 per channel
    float* ob = out + (size_t)img * ((size_t)BB * COUT * HW);
    const int y = y0 + ty, x = x0 + tx4 * 4;
#pragma unroll
    for (int j = 0; j < 8; j++) {
        float c0[4], c1[4];
#pragma unroll
        for (int px = 0; px < 4; px++) {
            unsigned plo, phi;
            asm("mov.b64 {%0,%1}, %2;" : "=r"(plo), "=r"(phi) : "l"(acc[px][j]));
            c0[px] = __uint_as_float(plo);
            c1[px] = __uint_as_float(phi);
        }
        float b0 = bias[co0 + 2 * j], b1 = bias[co0 + 2 * j + 1];
#pragma unroll
        for (int px = 0; px < 4; px++) {
            c0[px] += b0; c1[px] += b1;
            if constexpr (RELU) { c0[px] = fmaxf(c0[px], 0.f); c1[px] = fmaxf(c1[px], 0.f); }
        }
        float* o0 = ob + ((size_t)b * COUT + co0 + 2 * j) * HW + y * WW + x;
        float* o1 = ob + ((size_t)b * COUT + co0 + 2 * j + 1) * HW + y * WW + x;
        *reinterpret_cast<float4*>(o0) = make_float4(c0[0], c0[1], c0[2], c0[3]);
        *reinterpret_cast<float4*>(o1) = make_float4(c1[0], c1[1], c1[2], c1[3]);
    }
}

// ============ packed-f32x2 final conv: 64 -> 2, +bias +residual ==============
// block 256 thr; tile 64x16 px; thread = 4 px x both output channels.
__global__ void __launch_bounds__(256)
final_k(const float* __restrict__ in,
        const float* __restrict__ wt,
        const float* __restrict__ bias,
        const float* __restrict__ res,
        float* __restrict__ out)
{
    constexpr int CIN = 64;
    constexpr int NC  = 32;                  // chunks of 2 planes
    constexpr int PL  = 1280;
    extern __shared__ float sm[];
    float* w_s  = sm;                        // 64*9*2 = 1152
    float* in_s = sm + 1152;                 // 2 * 2 * PL

    const int tid = threadIdx.x;
    const int tx4 = tid & 15;
    const int ty  = tid >> 4;
    const int b   = blockIdx.z;
    const int x0 = blockIdx.x * 64, y0 = blockIdx.y * 16;

    // stage weights: w_s[(ci*9+k)*2 + co]
    for (int i = tid; i < 1152; i += 256) {
        int co = i & 1;
        int k  = (i >> 1) % 9;
        int ci = i / 18;
        w_s[i] = wt[(co * CIN + ci) * 9 + k];
    }

    const float* inb = in + (size_t)b * CIN * HW;
    int goff[5], vsz[5];
#pragma unroll
    for (int j = 0; j < 5; j++) {
        int idx = tid + 256 * j;
        int r = idx / 68, cc = idx % 68;
        int gy = y0 + r - 1, gx = x0 + cc - 1;
        bool ok = (idx < 18 * 68) && (cc < 66) &&
                  gy >= 0 && gy < HH && gx >= 0 && gx < WW;
        goff[j] = ok ? (gy * WW + gx) : 0;
        vsz[j]  = ok ? 4 : 0;
    }
    const unsigned sbase = smem_u32(in_s);

    auto issue = [&](int c) {
        const unsigned cb = sbase + (unsigned)((c & 1) * 2 * PL) * 4u;
#pragma unroll
        for (int p = 0; p < 2; p++) {
            const float* src = inb + (size_t)(c * 2 + p) * HW;
#pragma unroll
            for (int j = 0; j < 5; j++)
                cp4(cb + (unsigned)(p * PL + tid + 256 * j) * 4u,
                    src + goff[j], vsz[j]);
        }
        cp_commit();
    };

    ull acc[4];
#pragma unroll
    for (int px = 0; px < 4; px++) acc[px] = 0ULL;

    issue(0);

    for (int c = 0; c < NC; c++) {
        cp_wait0();
        __syncthreads();
        if (c + 1 < NC) issue(c + 1);

        const float* buf = in_s + (c & 1) * 2 * PL;
#pragma unroll
        for (int p = 0; p < 2; p++) {
            const float* wpl = w_s + (size_t)(c * 2 + p) * 18;
#pragma unroll
            for (int ky = 0; ky < 3; ky++) {
                const float* rp = buf + p * PL + (ty + ky) * 68 + tx4 * 4;
                float4 lo = *reinterpret_cast<const float4*>(rp);
                float2 hi = *reinterpret_cast<const float2*>(rp + 4);
                ull dv[6];
                dv[0] = dupf(lo.x); dv[1] = dupf(lo.y); dv[2] = dupf(lo.z);
                dv[3] = dupf(lo.w); dv[4] = dupf(hi.x); dv[5] = dupf(hi.y);
#pragma unroll
                for (int kx = 0; kx < 3; kx++) {
                    ull wp = *reinterpret_cast<const ull*>(wpl + (ky * 3 + kx) * 2);
#pragma unroll
                    for (int px = 0; px < 4; px++)
                        asm("fma.rn.f32x2 %0, %1, %2, %0;"
                            : "+l"(acc[px]) : "l"(dv[kx + px]), "l"(wp));
                }
            }
        }
        __syncthreads();
    }

    // epilogue: unpack (co0, co1), add bias + residual, store float4 per ch
    const int y = y0 + ty, x = x0 + tx4 * 4;
    const int pix = y * WW + x;
    float c0[4], c1[4];
#pragma unroll
    for (int px = 0; px < 4; px++) {
        unsigned plo, phi;
        asm("mov.b64 {%0,%1}, %2;" : "=r"(plo), "=r"(phi) : "l"(acc[px]));
        c0[px] = __uint_as_float(plo);
        c1[px] = __uint_as_float(phi);
    }
    float b0 = bias[0], b1 = bias[1];
    float4 r0 = *reinterpret_cast<const float4*>(res + ((size_t)b * 2 + 0) * HW + pix);
    float4 r1 = *reinterpret_cast<const float4*>(res + ((size_t)b * 2 + 1) * HW + pix);
    float4 o0 = make_float4(c0[0] + b0 + r0.x, c0[1] + b0 + r0.y,
                            c0[2] + b0 + r0.z, c0[3] + b0 + r0.w);
    float4 o1 = make_float4(c1[0] + b1 + r1.x, c1[1] + b1 + r1.y,
                            c1[2] + b1 + r1.z, c1[3] + b1 + r1.w);
    *reinterpret_cast<float4*>(out + ((size_t)b * 2 + 0) * HW + pix) = o0;
    *reinterpret_cast<float4*>(out + ((size_t)b * 2 + 1) * HW + pix) = o1;
}

// ---------------- bilinear warp of f2 by initial flow (border clamp) ---------
__global__ void warp_k(const float* __restrict__ f2,
                       const float* __restrict__ flow,
                       float* __restrict__ f2w)
{
    int x = blockIdx.x * 32 + (threadIdx.x & 31);
    int y = blockIdx.y * 8 + (threadIdx.x >> 5);
    int b = blockIdx.z;
    int pix = y * WW + x;
    float fx = (float)x + flow[((size_t)b * 2 + 0) * HW + pix];
    float fy = (float)y + flow[((size_t)b * 2 + 1) * HW + pix];
    fx = fminf(fmaxf(fx, 0.f), (float)(WW - 1));
    fy = fminf(fmaxf(fy, 0.f), (float)(HH - 1));
    float x0f = floorf(fx), y0f = floorf(fy);
    int x0 = (int)x0f, y0i = (int)y0f;
    int x1 = min(x0 + 1, WW - 1), y1 = min(y0i + 1, HH - 1);
    float wx = fx - x0f, wy = fy - y0f;
    float w00 = (1.f - wx) * (1.f - wy), w01 = wx * (1.f - wy);
    float w10 = (1.f - wx) * wy,        w11 = wx * wy;
    const float* fb = f2 + (size_t)b * 32 * HW;
    float* ob = f2w + (size_t)b * 32 * HW + pix;
#pragma unroll 8
    for (int c = 0; c < 32; c++) {
        const float* p = fb + (size_t)c * HW;
        float v = w00 * p[y0i * WW + x0] + w01 * p[y0i * WW + x1]
                + w10 * p[y1  * WW + x0] + w11 * p[y1  * WW + x1];
        ob[(size_t)c * HW] = v;
    }
}

// ---------------- cost volume: 2 px/thread, packed FFMA2; folds flow concat ---
__global__ void __launch_bounds__(128)
costvol_k(const float* __restrict__ f1,
          const float* __restrict__ f2w,
          const float* __restrict__ flow,
          float* __restrict__ cv)
{
    extern __shared__ float s[]; // 32*16*40
    const int tid = threadIdx.x;
    const int txi = tid & 15;
    const int ty  = tid >> 4;
    const int b = blockIdx.z;
    const int x0 = blockIdx.x * 32, y0 = blockIdx.y * 8;
    const float* f2b = f2w + (size_t)b * 32 * HW;
    for (int i = tid; i < 32 * 16 * 40; i += 128) {
        int c  = i / 640;
        int r  = (i % 640) / 40;
        int cc = i % 640 % 40;
        int gy = min(max(y0 + r - 4, 0), HH - 1);
        int gx = min(max(x0 + cc - 4, 0), WW - 1);
        s[i] = f2b[(size_t)c * HW + gy * WW + gx];
    }
    __syncthreads();

    const int y = y0 + ty, x = x0 + txi * 2;
    const int pix = y * WW + x;

    ull f1p[32];
    const float* f1b = f1 + (size_t)b * 32 * HW + pix;
#pragma unroll
    for (int c = 0; c < 32; c++)
        f1p[c] = *reinterpret_cast<const ull*>(f1b + (size_t)c * HW);

    float* cvb = cv + (size_t)b * 83 * HW + pix;

    for (int dy = 0; dy < 9; dy++) {
        ull acc[9];
#pragma unroll
        for (int dx = 0; dx < 9; dx++) acc[dx] = 0ULL;

        const float* rowp = s + (ty + dy) * 40 + txi * 2;
        for (int c = 0; c < 32; c++) {
            const float* sp = rowp + c * 640;
            float2 L0 = *reinterpret_cast<const float2*>(sp);
            float2 L1 = *reinterpret_cast<const float2*>(sp + 2);
            float2 L2 = *reinterpret_cast<const float2*>(sp + 4);
            float2 L3 = *reinterpret_cast<const float2*>(sp + 6);
            float2 L4 = *reinterpret_cast<const float2*>(sp + 8);
            ull P0 = *reinterpret_cast<const ull*>(&L0);
            ull P2 = *reinterpret_cast<const ull*>(&L1);
            ull P4 = *reinterpret_cast<const ull*>(&L2);
            ull P6 = *reinterpret_cast<const ull*>(&L3);
            ull P8 = *reinterpret_cast<const ull*>(&L4);
            ull P1, P3, P5, P7;
            asm("mov.b64 %0, {%1,%2};" : "=l"(P1)
                : "r"(__float_as_uint(L0.y)), "r"(__float_as_uint(L1.x)));
            asm("mov.b64 %0, {%1,%2};" : "=l"(P3)
                : "r"(__float_as_uint(L1.y)), "r"(__float_as_uint(L2.x)));
            asm("mov.b64 %0, {%1,%2};" : "=l"(P5)
                : "r"(__float_as_uint(L2.y)), "r"(__float_as_uint(L3.x)));
            asm("mov.b64 %0, {%1,%2};" : "=l"(P7)
                : "r"(__float_as_uint(L3.y)), "r"(__float_as_uint(L4.x)));
            ull fp = f1p[c];
            asm("fma.rn.f32x2 %0, %1, %2, %0;" : "+l"(acc[0]) : "l"(fp), "l"(P0));
            asm("fma.rn.f32x2 %0, %1, %2, %0;" : "+l"(acc[1]) : "l"(fp), "l"(P1));
            asm("fma.rn.f32x2 %0, %1, %2, %0;" : "+l"(acc[2]) : "l"(fp), "l"(P2));
            asm("fma.rn.f32x2 %0, %1, %2, %0;" : "+l"(acc[3]) : "l"(fp), "l"(P3));
            asm("fma.rn.f32x2 %0, %1, %2, %0;" : "+l"(acc[4]) : "l"(fp), "l"(P4));
            asm("fma.rn.f32x2 %0, %1, %2, %0;" : "+l"(acc[5]) : "l"(fp), "l"(P5));
            asm("fma.rn.f32x2 %0, %1, %2, %0;" : "+l"(acc[6]) : "l"(fp), "l"(P6));
            asm("fma.rn.f32x2 %0, %1, %2, %0;" : "+l"(acc[7]) : "l"(fp), "l"(P7));
            asm("fma.rn.f32x2 %0, %1, %2, %0;" : "+l"(acc[8]) : "l"(fp), "l"(P8));
        }
#pragma unroll
        for (int dx = 0; dx < 9; dx++) {
            unsigned plo, phi;
            asm("mov.b64 {%0,%1}, %2;" : "=r"(plo), "=r"(phi) : "l"(acc[dx]));
            *reinterpret_cast<float2*>(cvb + (size_t)(dy * 9 + dx) * HW) =
                make_float2(__uint_as_float(plo), __uint_as_float(phi));
        }
    }

    const float* flb = flow + (size_t)b * 2 * HW + pix;
    *reinterpret_cast<float2*>(cvb + (size_t)81 * HW) =
        *reinterpret_cast<const float2*>(flb);
    *reinterpret_cast<float2*>(cvb + (size_t)82 * HW) =
        *reinterpret_cast<const float2*>(flb + HW);
}

// ---------------- host launch -------------------------------------------------
static inline int smem_p2(int cin) {
    int cinp = (cin + 1) & ~1;
    return (cinp * 144 + 4 * 2 * 1280) * 4;
}

extern "C" void kernel_launch(void* const* d_in, const int* in_sizes, int n_in,
                              void* d_out, int out_size)
{
    const float* feat1 = (const float*)d_in[0];
    const float* feat2 = (const float*)d_in[1];
    const float* iflow = (const float*)d_in[2];
    const float* fW1 = (const float*)d_in[3];  const float* fb1 = (const float*)d_in[4];
    const float* fW2 = (const float*)d_in[5];  const float* fb2 = (const float*)d_in[6];
    const float* fW3 = (const float*)d_in[7];  const float* fb3 = (const float*)d_in[8];
    const float* rW1 = (const float*)d_in[9];  const float* rb1 = (const float*)d_in[10];
    const float* rW2 = (const float*)d_in[11]; const float* rb2 = (const float*)d_in[12];
    const float* rW3 = (const float*)d_in[13]; const float* rb3 = (const float*)d_in[14];
    const float* rW4 = (const float*)d_in[15]; const float* rb4 = (const float*)d_in[16];
    float* out = (float*)d_out;

    float *ta, *tb, *ff, *f2w, *cv, *h1, *h2, *wr;
    cudaGetSymbolAddress((void**)&ta,  g_ta);
    cudaGetSymbolAddress((void**)&tb,  g_tb);
    cudaGetSymbolAddress((void**)&ff,  g_ff);
    cudaGetSymbolAddress((void**)&f2w, g_f2w);
    cudaGetSymbolAddress((void**)&cv,  g_cv);
    cudaGetSymbolAddress((void**)&h1,  g_h1);
    cudaGetSymbolAddress((void**)&h2,  g_h2);
    cudaGetSymbolAddress((void**)&wr,  g_wr);

    cudaFuncSetAttribute((const void*)conv3x3_p2<3, 64, true, 2>,
                         cudaFuncAttributeMaxDynamicSharedMemorySize, smem_p2(3));
    cudaFuncSetAttribute((const void*)conv3x3_p2<64, 64, true, 2>,
                         cudaFuncAttributeMaxDynamicSharedMemorySize, smem_p2(64));
    cudaFuncSetAttribute((const void*)conv3x3_p2<64, 32, true, 2>,
                         cudaFuncAttributeMaxDynamicSharedMemorySize, smem_p2(64));
    cudaFuncSetAttribute((const void*)conv3x3_p2<83, 128, true, 1>,
                         cudaFuncAttributeMaxDynamicSharedMemorySize, smem_p2(83));
    cudaFuncSetAttribute((const void*)conv3x3_p2<128, 128, true, 1>,
                         cudaFuncAttributeMaxDynamicSharedMemorySize, smem_p2(128));
    cudaFuncSetAttribute((const void*)conv3x3_p2<128, 64, true, 1>,
                         cudaFuncAttributeMaxDynamicSharedMemorySize, smem_p2(128));
    cudaFuncSetAttribute((const void*)costvol_k,
                         cudaFuncAttributeMaxDynamicSharedMemorySize, 32 * 16 * 40 * 4);

    dim3 blk(256);
    const int PXg = WW / 64, PYg = HH / 16;  // 7, 16 (conv grid)
    const int SX = WW / 32, SY = HH / 8;     // 14, 32 (warp/costvol grid)

    // ---- weight reorders (tiny, once per launch) ----
    auto wre = [&](const float* w, int off, int cin, int cout) {
        int cinp = (cin + 1) & ~1;
        int n = (cout / 16) * cinp * 144;
        wreorder_k<<<(n + 255) / 256, 256>>>(w, wr + off, cin, cinp, n);
    };
    wre(fW1, WR_C1, 3, 64);
    wre(fW2, WR_C2, 64, 64);
    wre(fW3, WR_C3, 64, 32);
    wre(rW1, WR_R1, 83, 128);
    wre(rW2, WR_R2, 128, 128);
    wre(rW3, WR_R3, 128, 64);

    // ---- feature extraction (both images per launch) ----
    conv3x3_p2<3, 64, true, 2><<<dim3(PXg, PYg, 2 * BB * 4), blk, smem_p2(3)>>>(
        feat1, feat2, wr + WR_C1, fb1, ta);
    conv3x3_p2<64, 64, true, 2><<<dim3(PXg, PYg, 2 * BB * 4), blk, smem_p2(64)>>>(
        ta, ta + (size_t)BB * 64 * HW, wr + WR_C2, fb2, tb);
    conv3x3_p2<64, 32, true, 2><<<dim3(PXg, PYg, 2 * BB * 2), blk, smem_p2(64)>>>(
        tb, tb + (size_t)BB * 64 * HW, wr + WR_C3, fb3, ff);

    const float* f1 = ff;
    const float* f2 = ff + (size_t)BB * 32 * HW;

    // ---- warp + cost volume (+ flow concat) ----
    warp_k<<<dim3(SX, SY, BB), blk>>>(f2, iflow, f2w);
    costvol_k<<<dim3(SX, SY, BB), dim3(128), 32 * 16 * 40 * 4>>>(f1, f2w, iflow, cv);

    // ---- refinement ----
    conv3x3_p2<83, 128, true, 1><<<dim3(PXg, PYg, BB * 8), blk, smem_p2(83)>>>(
        cv, cv, wr + WR_R1, rb1, h1);
    conv3x3_p2<128, 128, true, 1><<<dim3(PXg, PYg, BB * 8), blk, smem_p2(128)>>>(
        h1, h1, wr + WR_R2, rb2, h2);
    conv3x3_p2<128, 64, true, 1><<<dim3(PXg, PYg, BB * 4), blk, smem_p2(128)>>>(
        h2, h2, wr + WR_R3, rb3, ta);
    final_k<<<dim3(PXg, PYg, BB), blk, (1152 + 2 * 2 * 1280) * 4>>>(
        ta, rW4, rb4, iflow, out);
}